// round 1
// baseline (speedup 1.0000x reference)
#include <cuda_runtime.h>
#include <cuda_bf16.h>

#define N_NODES 50000
#define N_EDGES 800000
#define IN_FEAT 512
#define HIDDEN  64
#define N_CLASS 16
#define KC      64

// Scratch (device globals — no allocation allowed)
__device__ float g_h0[N_NODES * HIDDEN];   // x @ W1
__device__ float g_h [N_NODES * HIDDEN];   // A @ h0 + b1 (pre-relu)
__device__ float g_z [N_NODES * N_CLASS];  // relu(h) @ W2
__device__ float g_l [N_NODES * N_CLASS];  // A @ z + b2 (logits)

// ---------------------------------------------------------------------------
// init: g_h <- broadcast b1, g_l <- broadcast b2
// ---------------------------------------------------------------------------
__global__ void init_kernel(const float* __restrict__ b1,
                            const float* __restrict__ b2) {
    int i = blockIdx.x * blockDim.x + threadIdx.x;
    if (i < N_NODES * HIDDEN)  g_h[i] = b1[i & (HIDDEN - 1)];
    if (i < N_NODES * N_CLASS) g_l[i] = b2[i & (N_CLASS - 1)];
}

// ---------------------------------------------------------------------------
// GEMM1: g_h0 = x @ W1   (50000x512 @ 512x64)
// Block: 32 rows x 64 cols, 256 threads (32 x 8).
// Each thread: 4 rows x 2 cols register tile.
// ---------------------------------------------------------------------------
__global__ __launch_bounds__(256)
void gemm1_kernel(const float* __restrict__ x, const float* __restrict__ W1) {
    __shared__ float Ws[KC][HIDDEN];   // 16 KB
    __shared__ float xs[32][KC];       // 8 KB

    const int cp  = threadIdx.x;              // 0..31 -> cols 2cp, 2cp+1
    const int rq  = threadIdx.y;               // 0..7  -> rows 4rq..4rq+3
    const int tid = rq * 32 + cp;
    const int row0 = blockIdx.x * 32;

    float acc[4][2] = {};

    for (int k0 = 0; k0 < IN_FEAT; k0 += KC) {
        // Load W chunk: KC*64 floats = 1024 float4, 4 per thread
        #pragma unroll
        for (int i = 0; i < 4; i++) {
            int idx = tid + i * 256;          // float4 index 0..1023
            int kk = idx >> 4;                // 16 float4 per row
            int qq = idx & 15;
            reinterpret_cast<float4*>(&Ws[kk][0])[qq] =
                reinterpret_cast<const float4*>(&W1[(size_t)(k0 + kk) * HIDDEN])[qq];
        }
        // Load x chunk: 32 rows x KC = 512 float4, 2 per thread
        #pragma unroll
        for (int i = 0; i < 2; i++) {
            int idx = tid + i * 256;          // 0..511
            int rr = idx >> 4;                // 16 float4 per row
            int qq = idx & 15;
            int grow = row0 + rr;
            float4 v = make_float4(0.f, 0.f, 0.f, 0.f);
            if (grow < N_NODES)
                v = reinterpret_cast<const float4*>(&x[(size_t)grow * IN_FEAT + k0])[qq];
            reinterpret_cast<float4*>(&xs[rr][0])[qq] = v;
        }
        __syncthreads();

        #pragma unroll
        for (int k = 0; k < KC; k++) {
            float2 w = *reinterpret_cast<const float2*>(&Ws[k][cp * 2]);
            #pragma unroll
            for (int r = 0; r < 4; r++) {
                float xv = xs[rq * 4 + r][k];
                acc[r][0] = fmaf(xv, w.x, acc[r][0]);
                acc[r][1] = fmaf(xv, w.y, acc[r][1]);
            }
        }
        __syncthreads();
    }

    #pragma unroll
    for (int r = 0; r < 4; r++) {
        int grow = row0 + rq * 4 + r;
        if (grow < N_NODES) {
            g_h0[(size_t)grow * HIDDEN + cp * 2]     = acc[r][0];
            g_h0[(size_t)grow * HIDDEN + cp * 2 + 1] = acc[r][1];
        }
    }
}

// ---------------------------------------------------------------------------
// SpMM1: g_h[dst] += ew * g_h0[src]   (64 features, one warp per edge)
// ---------------------------------------------------------------------------
__global__ __launch_bounds__(256)
void spmm1_kernel(const int* __restrict__ src, const int* __restrict__ dst,
                  const float* __restrict__ ew) {
    int e    = (blockIdx.x * blockDim.x + threadIdx.x) >> 5;
    int lane = threadIdx.x & 31;
    if (e >= N_EDGES) return;
    int s = src[e];
    int d = dst[e];
    float w = ew[e];
    float2 v = *reinterpret_cast<const float2*>(&g_h0[(size_t)s * HIDDEN + lane * 2]);
    atomicAdd(&g_h[(size_t)d * HIDDEN + lane * 2],     v.x * w);
    atomicAdd(&g_h[(size_t)d * HIDDEN + lane * 2 + 1], v.y * w);
}

// ---------------------------------------------------------------------------
// GEMM2: g_z = relu(g_h) @ W2   (50000x64 @ 64x16)
// Block: 16 rows x 16 cols, 256 threads.
// ---------------------------------------------------------------------------
__global__ __launch_bounds__(256)
void gemm2_kernel(const float* __restrict__ W2) {
    __shared__ float Ws[HIDDEN][N_CLASS];   // 4 KB
    __shared__ float hs[16][HIDDEN + 1];    // padded

    const int tid = threadIdx.x;
    const int row0 = blockIdx.x * 16;

    for (int i = tid; i < HIDDEN * N_CLASS; i += 256)
        Ws[i >> 4][i & 15] = W2[i];

    for (int i = tid; i < 16 * HIDDEN; i += 256) {
        int rr = i >> 6, kk = i & 63;
        int grow = row0 + rr;
        hs[rr][kk] = (grow < N_NODES) ? fmaxf(g_h[(size_t)grow * HIDDEN + kk], 0.f) : 0.f;
    }
    __syncthreads();

    int r = tid >> 4, c = tid & 15;
    float acc = 0.f;
    #pragma unroll
    for (int k = 0; k < HIDDEN; k++)
        acc = fmaf(hs[r][k], Ws[k][c], acc);

    int grow = row0 + r;
    if (grow < N_NODES)
        g_z[(size_t)grow * N_CLASS + c] = acc;
}

// ---------------------------------------------------------------------------
// SpMM2: g_l[dst] += ew * g_z[src]   (16 classes, 16 lanes per edge)
// ---------------------------------------------------------------------------
__global__ __launch_bounds__(256)
void spmm2_kernel(const int* __restrict__ src, const int* __restrict__ dst,
                  const float* __restrict__ ew) {
    int t = blockIdx.x * blockDim.x + threadIdx.x;
    int e = t >> 4;
    int c = t & 15;
    if (e >= N_EDGES) return;
    int s = src[e];
    int d = dst[e];
    float w = ew[e];
    atomicAdd(&g_l[(size_t)d * N_CLASS + c], g_z[(size_t)s * N_CLASS + c] * w);
}

// ---------------------------------------------------------------------------
// Softmax over 16 classes, one thread per node.
// ---------------------------------------------------------------------------
__global__ __launch_bounds__(256)
void softmax_kernel(float* __restrict__ out) {
    int n = blockIdx.x * blockDim.x + threadIdx.x;
    if (n >= N_NODES) return;
    float v[N_CLASS];
    const float4* p = reinterpret_cast<const float4*>(&g_l[(size_t)n * N_CLASS]);
    #pragma unroll
    for (int i = 0; i < 4; i++) {
        float4 q = p[i];
        v[i * 4 + 0] = q.x; v[i * 4 + 1] = q.y; v[i * 4 + 2] = q.z; v[i * 4 + 3] = q.w;
    }
    float m = v[0];
    #pragma unroll
    for (int i = 1; i < N_CLASS; i++) m = fmaxf(m, v[i]);
    float sum = 0.f;
    #pragma unroll
    for (int i = 0; i < N_CLASS; i++) { v[i] = expf(v[i] - m); sum += v[i]; }
    float inv = 1.f / sum;
    float4* o = reinterpret_cast<float4*>(&out[(size_t)n * N_CLASS]);
    #pragma unroll
    for (int i = 0; i < 4; i++) {
        o[i] = make_float4(v[i * 4] * inv, v[i * 4 + 1] * inv,
                           v[i * 4 + 2] * inv, v[i * 4 + 3] * inv);
    }
}

// ---------------------------------------------------------------------------
extern "C" void kernel_launch(void* const* d_in, const int* in_sizes, int n_in,
                              void* d_out, int out_size) {
    const float* x   = (const float*)d_in[0];
    const int*   src = (const int*)  d_in[1];
    const int*   dst = (const int*)  d_in[2];
    const float* ew  = (const float*)d_in[3];
    const float* W1  = (const float*)d_in[4];
    const float* b1  = (const float*)d_in[5];
    const float* W2  = (const float*)d_in[6];
    const float* b2  = (const float*)d_in[7];
    float* out = (float*)d_out;

    // init biases into accumulators
    {
        int total = N_NODES * HIDDEN;
        init_kernel<<<(total + 255) / 256, 256>>>(b1, b2);
    }
    // GEMM1
    gemm1_kernel<<<(N_NODES + 31) / 32, dim3(32, 8)>>>(x, W1);
    // SpMM1 (warp per edge)
    {
        long long threads = (long long)N_EDGES * 32;
        spmm1_kernel<<<(unsigned)((threads + 255) / 256), 256>>>(src, dst, ew);
    }
    // GEMM2
    gemm2_kernel<<<(N_NODES + 15) / 16, 256>>>(W2);
    // SpMM2 (16 lanes per edge)
    {
        long long threads = (long long)N_EDGES * 16;
        spmm2_kernel<<<(unsigned)((threads + 255) / 256), 256>>>(src, dst, ew);
    }
    // Softmax
    softmax_kernel<<<(N_NODES + 255) / 256, 256>>>(out);
}

// round 2
// speedup vs baseline: 1.1779x; 1.1779x over previous
#include <cuda_runtime.h>
#include <cuda_bf16.h>

#define N_NODES 50000
#define N_EDGES 800000
#define IN_FEAT 512
#define HIDDEN  64
#define N_CLASS 16
#define KC      32
#define RB      256   // rows per block in gemm1

// Scratch (device globals — no allocation allowed)
__device__ float g_h0[N_NODES * HIDDEN];   // x @ W1
__device__ float g_h [N_NODES * HIDDEN];   // A @ h0 + b1 (pre-relu)
__device__ float g_z [N_NODES * N_CLASS];  // relu(h) @ W2
__device__ float g_l [N_NODES * N_CLASS];  // A @ z + b2 (logits)

__device__ __forceinline__ void red_add_v4(float* p, float4 v) {
    asm volatile("red.global.add.v4.f32 [%0], {%1,%2,%3,%4};"
                 :: "l"(p), "f"(v.x), "f"(v.y), "f"(v.z), "f"(v.w)
                 : "memory");
}

// ---------------------------------------------------------------------------
// init: g_h <- broadcast b1, g_l <- broadcast b2
// ---------------------------------------------------------------------------
__global__ void init_kernel(const float* __restrict__ b1,
                            const float* __restrict__ b2) {
    int i = blockIdx.x * blockDim.x + threadIdx.x;
    if (i < N_NODES * HIDDEN)  g_h[i] = b1[i & (HIDDEN - 1)];
    if (i < N_NODES * N_CLASS) g_l[i] = b2[i & (N_CLASS - 1)];
}

// ---------------------------------------------------------------------------
// GEMM1: g_h0 = x @ W1   (50000x512 @ 512x64)
// Block: 256 rows x 64 cols, 256 threads (32 x 8).
// Thread (tx,ty): rows tx+32*i (i=0..7), cols ty*8..ty*8+7 -> 8x8 reg tile.
// smem: xs transposed [KC][RB] (32KB), ws [KC][64] (8KB).
// ---------------------------------------------------------------------------
__global__ __launch_bounds__(256, 2)
void gemm1_kernel(const float* __restrict__ x, const float* __restrict__ W1) {
    __shared__ float  xs[KC][RB];          // 32 KB, transposed
    __shared__ float4 ws[KC][HIDDEN / 4];  // 8 KB

    const int tx  = threadIdx.x;           // 0..31
    const int ty  = threadIdx.y;           // 0..7
    const int tid = ty * 32 + tx;
    const int row0 = blockIdx.x * RB;

    // This thread's global x row for staging (one row per thread)
    const int ldrow = row0 + tid;
    const bool ldok = (ldrow < N_NODES);
    const float* xrow = x + (size_t)ldrow * IN_FEAT;

    float acc[8][8] = {};

    for (int k0 = 0; k0 < IN_FEAT; k0 += KC) {
        // Stage x chunk, transposing: thread tid loads 32 k-values of its row
        #pragma unroll
        for (int i = 0; i < KC / 4; i++) {
            float4 v = make_float4(0.f, 0.f, 0.f, 0.f);
            if (ldok)
                v = *reinterpret_cast<const float4*>(&xrow[k0 + i * 4]);
            xs[i * 4 + 0][tid] = v.x;
            xs[i * 4 + 1][tid] = v.y;
            xs[i * 4 + 2][tid] = v.z;
            xs[i * 4 + 3][tid] = v.w;
        }
        // Stage W chunk: KC*64 floats = 512 float4, 2 per thread
        #pragma unroll
        for (int j = 0; j < 2; j++) {
            int idx = tid + j * 256;           // 0..511
            int kk = idx >> 4;                 // 16 float4 per k-row
            int qq = idx & 15;
            ws[kk][qq] = reinterpret_cast<const float4*>(
                             &W1[(size_t)(k0 + kk) * HIDDEN])[qq];
        }
        __syncthreads();

        #pragma unroll
        for (int k = 0; k < KC; k++) {
            float4 wa = ws[k][ty * 2];         // cols ty*8..+3 (broadcast in warp)
            float4 wb = ws[k][ty * 2 + 1];     // cols ty*8+4..+7
            #pragma unroll
            for (int i = 0; i < 8; i++) {
                float xv = xs[k][tx + 32 * i]; // lane-contiguous, conflict-free
                acc[i][0] = fmaf(xv, wa.x, acc[i][0]);
                acc[i][1] = fmaf(xv, wa.y, acc[i][1]);
                acc[i][2] = fmaf(xv, wa.z, acc[i][2]);
                acc[i][3] = fmaf(xv, wa.w, acc[i][3]);
                acc[i][4] = fmaf(xv, wb.x, acc[i][4]);
                acc[i][5] = fmaf(xv, wb.y, acc[i][5]);
                acc[i][6] = fmaf(xv, wb.z, acc[i][6]);
                acc[i][7] = fmaf(xv, wb.w, acc[i][7]);
            }
        }
        __syncthreads();
    }

    #pragma unroll
    for (int i = 0; i < 8; i++) {
        int g = row0 + tx + 32 * i;
        if (g < N_NODES) {
            float* o = &g_h0[(size_t)g * HIDDEN + ty * 8];
            *reinterpret_cast<float4*>(o)     = make_float4(acc[i][0], acc[i][1], acc[i][2], acc[i][3]);
            *reinterpret_cast<float4*>(o + 4) = make_float4(acc[i][4], acc[i][5], acc[i][6], acc[i][7]);
        }
    }
}

// ---------------------------------------------------------------------------
// SpMM1: g_h[dst] += ew * g_h0[src]   (64 feats, 16 lanes/edge, float4 RED)
// ---------------------------------------------------------------------------
__global__ __launch_bounds__(256)
void spmm1_kernel(const int* __restrict__ src, const int* __restrict__ dst,
                  const float* __restrict__ ew) {
    int t = blockIdx.x * blockDim.x + threadIdx.x;
    int e = t >> 4;
    int f = (t & 15) << 2;
    if (e >= N_EDGES) return;
    int s   = __ldg(&src[e]);
    int d   = __ldg(&dst[e]);
    float w = __ldg(&ew[e]);
    float4 v = *reinterpret_cast<const float4*>(&g_h0[(size_t)s * HIDDEN + f]);
    red_add_v4(&g_h[(size_t)d * HIDDEN + f],
               make_float4(v.x * w, v.y * w, v.z * w, v.w * w));
}

// ---------------------------------------------------------------------------
// GEMM2: g_z = relu(g_h) @ W2   (50000x64 @ 64x16), thread per node.
// W2 broadcast from smem (warp-uniform reads), 16 reg accumulators.
// ---------------------------------------------------------------------------
__global__ __launch_bounds__(256)
void gemm2_kernel(const float* __restrict__ W2) {
    __shared__ float4 Ws[HIDDEN][N_CLASS / 4];   // 4 KB

    const int tid = threadIdx.x;
    // 64 rows x 4 float4 = 256 float4, one per thread
    {
        int kk = tid >> 2, qq = tid & 3;
        Ws[kk][qq] = reinterpret_cast<const float4*>(&W2[(size_t)kk * N_CLASS])[qq];
    }
    __syncthreads();

    int n = blockIdx.x * 256 + tid;
    if (n >= N_NODES) return;

    float acc[N_CLASS] = {};
    const float4* hrow = reinterpret_cast<const float4*>(&g_h[(size_t)n * HIDDEN]);
    #pragma unroll
    for (int kq = 0; kq < HIDDEN / 4; kq++) {
        float4 h4 = __ldg(&hrow[kq]);
        float hv[4] = {fmaxf(h4.x, 0.f), fmaxf(h4.y, 0.f),
                       fmaxf(h4.z, 0.f), fmaxf(h4.w, 0.f)};
        #pragma unroll
        for (int j = 0; j < 4; j++) {
            int k = kq * 4 + j;
            #pragma unroll
            for (int q = 0; q < 4; q++) {
                float4 w4 = Ws[k][q];
                acc[q * 4 + 0] = fmaf(hv[j], w4.x, acc[q * 4 + 0]);
                acc[q * 4 + 1] = fmaf(hv[j], w4.y, acc[q * 4 + 1]);
                acc[q * 4 + 2] = fmaf(hv[j], w4.z, acc[q * 4 + 2]);
                acc[q * 4 + 3] = fmaf(hv[j], w4.w, acc[q * 4 + 3]);
            }
        }
    }
    float4* o = reinterpret_cast<float4*>(&g_z[(size_t)n * N_CLASS]);
    #pragma unroll
    for (int q = 0; q < 4; q++)
        o[q] = make_float4(acc[q * 4], acc[q * 4 + 1], acc[q * 4 + 2], acc[q * 4 + 3]);
}

// ---------------------------------------------------------------------------
// SpMM2: g_l[dst] += ew * g_z[src]   (16 classes, 4 lanes/edge, float4 RED)
// ---------------------------------------------------------------------------
__global__ __launch_bounds__(256)
void spmm2_kernel(const int* __restrict__ src, const int* __restrict__ dst,
                  const float* __restrict__ ew) {
    int t = blockIdx.x * blockDim.x + threadIdx.x;
    int e = t >> 2;
    int c = (t & 3) << 2;
    if (e >= N_EDGES) return;
    int s   = __ldg(&src[e]);
    int d   = __ldg(&dst[e]);
    float w = __ldg(&ew[e]);
    float4 v = *reinterpret_cast<const float4*>(&g_z[(size_t)s * N_CLASS + c]);
    red_add_v4(&g_l[(size_t)d * N_CLASS + c],
               make_float4(v.x * w, v.y * w, v.z * w, v.w * w));
}

// ---------------------------------------------------------------------------
// Softmax over 16 classes, one thread per node.
// ---------------------------------------------------------------------------
__global__ __launch_bounds__(256)
void softmax_kernel(float* __restrict__ out) {
    int n = blockIdx.x * blockDim.x + threadIdx.x;
    if (n >= N_NODES) return;
    float v[N_CLASS];
    const float4* p = reinterpret_cast<const float4*>(&g_l[(size_t)n * N_CLASS]);
    #pragma unroll
    for (int i = 0; i < 4; i++) {
        float4 q = p[i];
        v[i * 4 + 0] = q.x; v[i * 4 + 1] = q.y; v[i * 4 + 2] = q.z; v[i * 4 + 3] = q.w;
    }
    float m = v[0];
    #pragma unroll
    for (int i = 1; i < N_CLASS; i++) m = fmaxf(m, v[i]);
    float sum = 0.f;
    #pragma unroll
    for (int i = 0; i < N_CLASS; i++) { v[i] = expf(v[i] - m); sum += v[i]; }
    float inv = 1.f / sum;
    float4* o = reinterpret_cast<float4*>(&out[(size_t)n * N_CLASS]);
    #pragma unroll
    for (int i = 0; i < 4; i++) {
        o[i] = make_float4(v[i * 4] * inv, v[i * 4 + 1] * inv,
                           v[i * 4 + 2] * inv, v[i * 4 + 3] * inv);
    }
}

// ---------------------------------------------------------------------------
extern "C" void kernel_launch(void* const* d_in, const int* in_sizes, int n_in,
                              void* d_out, int out_size) {
    const float* x   = (const float*)d_in[0];
    const int*   src = (const int*)  d_in[1];
    const int*   dst = (const int*)  d_in[2];
    const float* ew  = (const float*)d_in[3];
    const float* W1  = (const float*)d_in[4];
    const float* b1  = (const float*)d_in[5];
    const float* W2  = (const float*)d_in[6];
    const float* b2  = (const float*)d_in[7];
    float* out = (float*)d_out;

    {
        int total = N_NODES * HIDDEN;
        init_kernel<<<(total + 255) / 256, 256>>>(b1, b2);
    }
    gemm1_kernel<<<(N_NODES + RB - 1) / RB, dim3(32, 8)>>>(x, W1);
    {
        long long threads = (long long)N_EDGES * 16;
        spmm1_kernel<<<(unsigned)((threads + 255) / 256), 256>>>(src, dst, ew);
    }
    gemm2_kernel<<<(N_NODES + 255) / 256, 256>>>(W2);
    {
        long long threads = (long long)N_EDGES * 4;
        spmm2_kernel<<<(unsigned)((threads + 255) / 256), 256>>>(src, dst, ew);
    }
    softmax_kernel<<<(N_NODES + 255) / 256, 256>>>(out);
}